// round 7
// baseline (speedup 1.0000x reference)
#include <cuda_runtime.h>
#include <cuda_fp16.h>
#include <float.h>
#include <stdint.h>

#define Bsz  8
#define Cdim 128
#define Ndim 4096
#define Odim 256
#define KNN  16
#define FULLM 0xFFFFFFFFu

// ---------------- scratch (static device globals; no allocations) -------------
__device__ float g_net[Bsz * Cdim * Ndim];     // [b][c][n]      16 MB
__device__ float g_sq[Bsz * Ndim];             // [b][n]
__device__ int   g_idx[Bsz * Ndim * KNN];      // [b][n][k]       2 MB
__device__ float g_p1t[Bsz * Ndim * Odim];     // [b][n][o]      32 MB
__device__ float g_baset[Bsz * Ndim * Odim];   // [b][n][o]      32 MB
__device__ __half g_hi[Bsz * Ndim * Cdim];     // [b][n][c]       8 MB
__device__ float g_netT[Bsz * Ndim * Cdim];    // [b][n][c]      16 MB
__device__ uint32_t g_cand[Bsz * Ndim * 64];   // packed coarse top-64   8 MB

__device__ __forceinline__ uint32_t smem_u32(const void* p) {
    uint32_t a;
    asm("{ .reg .u64 t; cvta.to.shared.u64 t, %1; cvt.u32.u64 %0, t; }" : "=r"(a) : "l"(p));
    return a;
}
__device__ __forceinline__ void ldmx4(uint32_t* r, uint32_t addr) {
    asm volatile("ldmatrix.sync.aligned.m8n8.x4.shared.b16 {%0,%1,%2,%3}, [%4];"
        : "=r"(r[0]), "=r"(r[1]), "=r"(r[2]), "=r"(r[3]) : "r"(addr));
}
__device__ __forceinline__ void mma16816(float* c, const uint32_t* a,
                                         uint32_t b0, uint32_t b1) {
    asm volatile("mma.sync.aligned.m16n8k16.row.col.f32.f16.f16.f32 "
        "{%0,%1,%2,%3}, {%4,%5,%6,%7}, {%8,%9}, {%0,%1,%2,%3};"
        : "+f"(c[0]), "+f"(c[1]), "+f"(c[2]), "+f"(c[3])
        : "r"(a[0]), "r"(a[1]), "r"(a[2]), "r"(a[3]), "r"(b0), "r"(b1));
}

// ==============================================================================
// Kernel A: net = relu(w0 @ x + b0), fused sq[b][n] = sum_c net^2
// ==============================================================================
__global__ __launch_bounds__(256) void k_net(const float* __restrict__ x,
                                             const float* __restrict__ w0,
                                             const float* __restrict__ b0) {
    __shared__ float Ws[32][129];
    __shared__ float Ns[32][128];
    __shared__ float sqs[16][129];

    const int b  = blockIdx.y;
    const int n0 = blockIdx.x * 128;
    const int tid = threadIdx.x;
    const int tx = tid & 15;
    const int ty = tid >> 4;

    float acc[8][8];
    #pragma unroll
    for (int i = 0; i < 8; ++i)
        #pragma unroll
        for (int j = 0; j < 8; ++j) acc[i][j] = 0.f;

    for (int k0 = 0; k0 < 128; k0 += 32) {
        __syncthreads();
        #pragma unroll
        for (int i = 0; i < 16; ++i) {
            int idx = tid + i * 256;
            int cc = idx & 31, o = idx >> 5;
            Ws[cc][o] = w0[o * 128 + k0 + cc];
        }
        #pragma unroll
        for (int i = 0; i < 16; ++i) {
            int idx = tid + i * 256;
            int c = idx >> 7, n = idx & 127;
            Ns[c][n] = x[(b * 128 + k0 + c) * Ndim + n0 + n];
        }
        __syncthreads();
        #pragma unroll
        for (int kk = 0; kk < 32; ++kk) {
            float4 x0 = *(const float4*)&Ns[kk][tx * 8];
            float4 x1 = *(const float4*)&Ns[kk][tx * 8 + 4];
            float xr[8] = {x0.x, x0.y, x0.z, x0.w, x1.x, x1.y, x1.z, x1.w};
            #pragma unroll
            for (int i = 0; i < 8; ++i) {
                float wv = Ws[kk][ty * 8 + i];
                #pragma unroll
                for (int j = 0; j < 8; ++j) acc[i][j] += wv * xr[j];
            }
        }
    }

    float part[8];
    #pragma unroll
    for (int j = 0; j < 8; ++j) part[j] = 0.f;

    #pragma unroll
    for (int i = 0; i < 8; ++i) {
        int o = ty * 8 + i;
        float bv = __ldg(&b0[o]);
        float r[8];
        #pragma unroll
        for (int j = 0; j < 8; ++j) {
            r[j] = fmaxf(acc[i][j] + bv, 0.f);
            part[j] += r[j] * r[j];
        }
        int base = (b * 128 + o) * Ndim + n0 + tx * 8;
        float4 s0 = {r[0], r[1], r[2], r[3]};
        float4 s1 = {r[4], r[5], r[6], r[7]};
        *(float4*)&g_net[base]     = s0;
        *(float4*)&g_net[base + 4] = s1;
    }
    #pragma unroll
    for (int j = 0; j < 8; ++j) sqs[ty][tx * 8 + j] = part[j];
    __syncthreads();
    if (tid < 128) {
        float s = 0.f;
        #pragma unroll
        for (int r = 0; r < 16; ++r) s += sqs[r][tid];
        g_sq[b * Ndim + n0 + tid] = s;
    }
}

// ==============================================================================
// Kernel B: transpose + fp16 round: g_net[b][c][n] -> g_hi (fp16), g_netT (fp32)
// ==============================================================================
__global__ __launch_bounds__(256) void k_split() {
    __shared__ float s[32][33];
    const int b  = blockIdx.z;
    const int c0 = blockIdx.y * 32;
    const int n0 = blockIdx.x * 32;
    const int tx = threadIdx.x & 31;
    const int ty = threadIdx.x >> 5;    // 0..7

    #pragma unroll
    for (int i = 0; i < 4; ++i) {
        int c = ty + i * 8;
        s[c][tx] = g_net[(b * Cdim + c0 + c) * Ndim + n0 + tx];
    }
    __syncthreads();
    #pragma unroll
    for (int i = 0; i < 4; ++i) {
        int nl = ty + i * 8;
        float v = s[tx][nl];
        int dst = (b * Ndim + n0 + nl) * Cdim + c0 + tx;
        g_hi[dst]   = __float2half(v);
        g_netT[dst] = v;
    }
}

// ==============================================================================
// Kernel C v7: coarse kNN candidates. 1-pass fp16 gram (mma.sync), per-thread
// segmented packed top-16 lists in registers -> g_cand (64 candidates/query).
// grid (32, 8), 256 threads (8 warps), 2 CTAs/SM. M-tile = 64.
// ==============================================================================
#define PITCHB 272                     // 136 halves/row: conflict-free ldmatrix
#define SM_QHI 0                       // 128 x 272 B = 34816
#define SM_MHI 34816                   // 64 x 272 B  = 17408
#define SM_SQM (34816 + 17408)         // 64 floats
#define SM_TOT (SM_SQM + 256)

// Branchless insert of v into ascending 16-list (registers, static indices).
__device__ __forceinline__ void ins16(float (&ls)[16], float v) {
    int r = 0;
    #pragma unroll
    for (int i = 0; i < 16; ++i) r += (ls[i] <= v) ? 1 : 0;
    #pragma unroll
    for (int j = 15; j > 0; --j) {
        bool sh = (j > r);
        ls[j] = sh ? ls[j - 1] : ls[j];
    }
    #pragma unroll
    for (int j = 0; j < 16; ++j)
        if (j == r) ls[j] = v;
}

__global__ __launch_bounds__(256, 2) void k_knn() {
    extern __shared__ char smem[];
    const uint32_t sbase = smem_u32(smem);
    const int tid  = threadIdx.x;
    const int lane = tid & 31;
    const int wid  = tid >> 5;          // 0..7
    const int b    = blockIdx.y;
    const int n0   = blockIdx.x * 128;
    const int qbase = wid * 16;

    // Stage Q hi tile (128 x 128 fp16) once
    for (int i = tid; i < 2048; i += 256) {
        int row = i >> 4, c8 = (i & 15) * 8;
        uint4 v = *(const uint4*)(g_hi + (size_t)(b * Ndim + n0 + row) * Cdim + c8);
        *(uint4*)(smem + SM_QHI + row * PITCHB + c8 * 2) = v;
    }

    const uint32_t a_base = sbase + SM_QHI + (qbase + (lane & 15)) * PITCHB + ((lane >> 4) << 4);
    const uint32_t b_base = sbase + SM_MHI + ((lane & 7) + ((lane >> 4) << 3)) * PITCHB
                                  + (((lane >> 3) & 1) << 4);
    const float* sqm = (const float*)(smem + SM_SQM);

    float l0[16], l1[16];               // packed coarse top-16 (2 q-rows)
    #pragma unroll
    for (int i = 0; i < 16; ++i) { l0[i] = FLT_MAX; l1[i] = FLT_MAX; }

    for (int mt = 0; mt < 64; ++mt) {
        const int m0 = mt * 64;
        __syncthreads();
        // load M hi tile (64 x 128 fp16)
        for (int i = tid; i < 1024; i += 256) {
            int row = i >> 4, c8 = (i & 15) * 8;
            uint4 v = *(const uint4*)(g_hi + (size_t)(b * Ndim + m0 + row) * Cdim + c8);
            *(uint4*)(smem + SM_MHI + row * PITCHB + c8 * 2) = v;
        }
        if (tid < 64) ((float*)(smem + SM_SQM))[tid] = g_sq[b * Ndim + m0 + tid];
        __syncthreads();

        float c[8][4];
        #pragma unroll
        for (int t = 0; t < 8; ++t)
            #pragma unroll
            for (int e = 0; e < 4; ++e) c[t][e] = 0.f;

        #pragma unroll
        for (int ks = 0; ks < 8; ++ks) {
            uint32_t ra[4];
            ldmx4(ra, a_base + ks * 32);
            #pragma unroll
            for (int tp = 0; tp < 4; ++tp) {
                uint32_t rb[4];
                ldmx4(rb, b_base + tp * (16 * PITCHB) + ks * 32);
                mma16816(c[2 * tp],     ra, rb[0], rb[1]);
                mma16816(c[2 * tp + 1], ra, rb[2], rb[3]);
            }
        }

        // epilogue: packed key = (key & ~0xFFF) | m ; insert into segment lists
        const int mo = (lane & 3) * 2;
        #pragma unroll
        for (int t = 0; t < 8; ++t) {
            int m = t * 8 + mo;
            float s0 = sqm[m], s1 = sqm[m + 1];
            float k0 = s0 - 2.f * c[t][0];
            float k1 = s1 - 2.f * c[t][1];
            float k2 = s0 - 2.f * c[t][2];
            float k3 = s1 - 2.f * c[t][3];
            uint32_t mg0 = (uint32_t)(m0 + m), mg1 = mg0 + 1;
            float p0 = __uint_as_float((__float_as_uint(k0) & 0xFFFFF000u) | mg0);
            float p1 = __uint_as_float((__float_as_uint(k1) & 0xFFFFF000u) | mg1);
            float p2 = __uint_as_float((__float_as_uint(k2) & 0xFFFFF000u) | mg0);
            float p3 = __uint_as_float((__float_as_uint(k3) & 0xFFFFF000u) | mg1);
            if (p0 < l0[15]) ins16(l0, p0);
            if (p1 < l0[15]) ins16(l0, p1);
            if (p2 < l1[15]) ins16(l1, p2);
            if (p3 < l1[15]) ins16(l1, p3);
        }
    }

    // write candidates: query q, segment s -> g_cand[b][q][s*16 .. s*16+15]
    {
        const int s = lane & 3;
        const int q0 = n0 + qbase + (lane >> 2);
        uint32_t* c0 = g_cand + ((size_t)(b * Ndim + q0)) * 64 + s * 16;
        uint32_t* c1 = g_cand + ((size_t)(b * Ndim + q0 + 8)) * 64 + s * 16;
        #pragma unroll
        for (int i = 0; i < 16; ++i) {
            c0[i] = __float_as_uint(l0[i]);
            c1[i] = __float_as_uint(l1[i]);
        }
    }
}

// ==============================================================================
// Kernel C2: exact fp32 rescore of 64 candidates/query + exact top-17 extract.
// grid (Ndim/8, Bsz), 256 threads: warp w handles query blockIdx.x*8 + w.
// ==============================================================================
__global__ __launch_bounds__(256) void k_resc() {
    const int lane = threadIdx.x & 31;
    const int wid  = threadIdx.x >> 5;
    const int b    = blockIdx.y;
    const int q    = blockIdx.x * 8 + wid;

    const float4 qv = *(const float4*)&g_netT[(size_t)(b * Ndim + q) * Cdim + lane * 4];
    const uint32_t* crow = g_cand + ((size_t)(b * Ndim + q)) * 64;
    uint32_t pk0 = crow[lane];
    uint32_t pk1 = crow[32 + lane];

    float part[64];
    #pragma unroll
    for (int ci = 0; ci < 64; ++ci) {
        uint32_t pk = __shfl_sync(FULLM, (ci < 32) ? pk0 : pk1, ci & 31);
        int m = (int)(pk & 0xFFFu);
        float4 mv = *(const float4*)&g_netT[(size_t)(b * Ndim + m) * Cdim + lane * 4];
        part[ci] = qv.x * mv.x + qv.y * mv.y + qv.z * mv.z + qv.w * mv.w;
    }
    // butterfly reductions: afterwards every lane holds full dot for each ci
    #pragma unroll
    for (int ci = 0; ci < 64; ++ci) {
        float v = part[ci];
        v += __shfl_xor_sync(FULLM, v, 16);
        v += __shfl_xor_sync(FULLM, v, 8);
        v += __shfl_xor_sync(FULLM, v, 4);
        v += __shfl_xor_sync(FULLM, v, 2);
        v += __shfl_xor_sync(FULLM, v, 1);
        part[ci] = v;
    }
    // lane owns candidates ci=lane and ci=lane+32
    float da = 0.f, db = 0.f;
    #pragma unroll
    for (int ci = 0; ci < 32; ++ci) da = (ci == lane) ? part[ci] : da;
    #pragma unroll
    for (int ci = 32; ci < 64; ++ci) db = (ci - 32 == lane) ? part[ci] : db;

    int ma = (int)(pk0 & 0xFFFu);
    int mb = (int)(pk1 & 0xFFFu);
    float ka = __ldg(&g_sq[b * Ndim + ma]) - 2.f * da;
    float kb = __ldg(&g_sq[b * Ndim + mb]) - 2.f * db;

    int* orow = g_idx + ((size_t)(b * Ndim + q)) * KNN;
    #pragma unroll 1
    for (int t = 0; t < 17; ++t) {
        bool sa = (ka < kb) || (ka == kb && ma < mb);
        float lk = sa ? ka : kb;
        int   lm = sa ? ma : mb;
        #pragma unroll
        for (int d = 16; d > 0; d >>= 1) {
            float ok = __shfl_xor_sync(FULLM, lk, d);
            int   om = __shfl_xor_sync(FULLM, lm, d);
            bool take = (ok < lk) || (ok == lk && om < lm);
            lk = take ? ok : lk;
            lm = take ? om : lm;
        }
        if (t > 0 && lane == 0) orow[t - 1] = lm;   // t=0 = self (strict min) dropped
        if (ma == lm) ka = FLT_MAX;
        if (mb == lm) kb = FLT_MAX;
    }
}

// ==============================================================================
// Kernel D: two independent 64-reg GEMMs selected by z&1:
//   which=0: p1   = w1@net                  -> g_p1t  [b][n][o]
//   which=1: base = (w2-w1)@net + (b1+b2)   -> g_baset[b][n][o]
// ==============================================================================
__global__ __launch_bounds__(256) void k_proj(const float* __restrict__ w1,
                                              const float* __restrict__ b1,
                                              const float* __restrict__ w2,
                                              const float* __restrict__ b2) {
    __shared__ float Wc[16][129];   // [c-chunk][o]
    __shared__ float Ns[16][128];   // [c-chunk][n]

    const int b     = blockIdx.y;
    const int n0    = blockIdx.x * 128;
    const int which = blockIdx.z & 1;
    const int oz    = (blockIdx.z >> 1) * 128;
    const int tid = threadIdx.x;
    const int tx = tid & 15;        // o group
    const int ty = tid >> 4;        // n group

    float a[8][8];
    #pragma unroll
    for (int j = 0; j < 8; ++j)
        #pragma unroll
        for (int i = 0; i < 8; ++i) a[j][i] = 0.f;

    for (int k0 = 0; k0 < 128; k0 += 16) {
        __syncthreads();
        #pragma unroll
        for (int i = 0; i < 8; ++i) {
            int idx = tid + i * 256;
            int cc = idx & 15, o = idx >> 4;
            float wv = w1[(oz + o) * 128 + k0 + cc];
            if (which) wv = w2[(oz + o) * 128 + k0 + cc] - wv;
            Wc[cc][o] = wv;
        }
        #pragma unroll
        for (int i = 0; i < 8; ++i) {
            int idx = tid + i * 256;
            int c = idx >> 7, n = idx & 127;
            Ns[c][n] = g_net[(b * 128 + k0 + c) * Ndim + n0 + n];
        }
        __syncthreads();
        #pragma unroll
        for (int kk = 0; kk < 16; ++kk) {
            float4 nv0 = *(const float4*)&Ns[kk][ty * 8];
            float4 nv1 = *(const float4*)&Ns[kk][ty * 8 + 4];
            float nr[8] = {nv0.x, nv0.y, nv0.z, nv0.w, nv1.x, nv1.y, nv1.z, nv1.w};
            float wr[8];
            #pragma unroll
            for (int i = 0; i < 8; ++i) wr[i] = Wc[kk][tx * 8 + i];
            #pragma unroll
            for (int j = 0; j < 8; ++j)
                #pragma unroll
                for (int i = 0; i < 8; ++i) a[j][i] += nr[j] * wr[i];
        }
    }

    float bb[8];
    #pragma unroll
    for (int i = 0; i < 8; ++i) {
        int o = oz + tx * 8 + i;
        bb[i] = which ? (__ldg(&b1[o]) + __ldg(&b2[o])) : 0.f;
    }
    float* dst = which ? g_baset : g_p1t;
    #pragma unroll
    for (int j = 0; j < 8; ++j) {
        int n = n0 + ty * 8 + j;
        int base = (b * Ndim + n) * Odim + oz + tx * 8;
        float4 v0 = {a[j][0] + bb[0], a[j][1] + bb[1], a[j][2] + bb[2], a[j][3] + bb[3]};
        float4 v1 = {a[j][4] + bb[4], a[j][5] + bb[5], a[j][6] + bb[6], a[j][7] + bb[7]};
        *(float4*)&dst[base]     = v0;
        *(float4*)&dst[base + 4] = v1;
    }
}

// ==============================================================================
// Kernel E: y[b,o,n] = relu(max_k (base[b,n,o] + p1t[b,idx[n,k],o]))
// ==============================================================================
__global__ __launch_bounds__(256) void k_edge(float* __restrict__ out) {
    __shared__ int   idxs[32][16];
    __shared__ float ys[32][257];

    const int b  = blockIdx.y;
    const int n0 = blockIdx.x * 32;
    const int tid = threadIdx.x;

    #pragma unroll
    for (int i = 0; i < 2; ++i) {
        int j = tid + i * 256;
        idxs[j >> 4][j & 15] = g_idx[(b * Ndim + n0 + (j >> 4)) * KNN + (j & 15)];
    }
    __syncthreads();

    #pragma unroll 1
    for (int nn = 0; nn < 32; ++nn) {
        float v = g_baset[(b * Ndim + n0 + nn) * Odim + tid];
        float acc = -FLT_MAX;
        #pragma unroll
        for (int t = 0; t < 16; ++t) {
            int m = idxs[nn][t];
            acc = fmaxf(acc, v + g_p1t[(b * Ndim + m) * Odim + tid]);
        }
        ys[nn][tid] = fmaxf(acc, 0.f);
    }
    __syncthreads();

    #pragma unroll
    for (int i = 0; i < 32; ++i) {
        int j = tid + i * 256;
        int o = j >> 5, n = j & 31;
        out[(b * Odim + o) * Ndim + n0 + n] = ys[n][o];
    }
}

// ==============================================================================
extern "C" void kernel_launch(void* const* d_in, const int* in_sizes, int n_in,
                              void* d_out, int out_size) {
    const float *x = 0, *w0 = 0, *b0 = 0, *w1 = 0, *b1 = 0, *w2 = 0, *b2 = 0;
    for (int i = 0; i < n_in; ++i) {
        const float* p = (const float*)d_in[i];
        switch (in_sizes[i]) {
            case 4194304: x = p; break;
            case 16384:   w0 = p; break;
            case 128:     b0 = p; break;
            case 32768:   if (!w1) w1 = p; else w2 = p; break;
            case 256:     if (!b1) b1 = p; else b2 = p; break;
            default: break; // k, scale scalars
        }
    }
    float* out = (float*)d_out;

    cudaFuncSetAttribute(k_knn, cudaFuncAttributeMaxDynamicSharedMemorySize, SM_TOT);

    k_net  <<<dim3(32, 8),        256>>>(x, w0, b0);
    k_split<<<dim3(128, 4, 8),    256>>>();
    k_knn  <<<dim3(32, 8),        256, SM_TOT>>>();
    k_resc <<<dim3(Ndim / 8, 8),  256>>>();
    k_proj <<<dim3(32, 8, 4),     256>>>(w1, b1, w2, b2);
    k_edge <<<dim3(128, 8),       256>>>(out);
}